// round 7
// baseline (speedup 1.0000x reference)
#include <cuda_runtime.h>
#include <cuda_fp16.h>
#include <cstdint>

#define BB 256
#define II 1152
#define OO 10
#define DDO 16
#define DDI 8
#define OD 160       // OO*DDO
#define WS 12        // smem row stride (words), conflict-free

// k_hat tiling
#define ITH 32       // i per block (hat)
#define NTH 36       // II/ITH
#define RPT 4        // i staged per sync round
// k_route tiling
#define ITR 64       // i per block (route)
#define NTR 18       // II/ITR
#define NTMAX 72     // g_spart tile stride

// Scratch (device globals: allocation-free rule)
__device__ __half g_hat[(size_t)BB * II * OD];    // ~94.4 MB
__device__ float g_spart[(size_t)BB * NTMAX * OD];
__device__ float g_vsum[BB * OD];

// f32 -> tf32 bit pattern (rna). NB: tf32 destination must be a b32 register.
__device__ __forceinline__ unsigned tf32r(float f) {
    unsigned u;
    asm("cvt.rna.tf32.f32 %0, %1;" : "=r"(u) : "f"(f));
    return u;
}

// K1: hat = x @ W^T per (b,i) via mma.m16n8k8.tf32. Block: 32 b x ITH i x 160 od.
// Warp w: m-tile (w&1) of 16 b, od-range (w>>1)*40 .. +40 (5 n-tiles).
__global__ void __launch_bounds__(256) k_hat(const float* __restrict__ x,
                                             const float* __restrict__ w) {
    __shared__ unsigned ws[RPT][OD * WS];    // W[i]: 160 rows x 8 (stride 12), tf32 bits
    __shared__ unsigned xs[RPT][32 * WS];    // x[i]:  32 rows x 8 (stride 12), tf32 bits
    const int t = threadIdx.x;
    const int warp = t >> 5, lane = t & 31;
    const int gid = lane >> 2, tig = lane & 3;   // groupID, thread-in-group
    const int mtile = warp & 1;
    const int od0w = (warp >> 1) * 40;
    const int i0 = blockIdx.x * ITH;
    const int b0 = blockIdx.y * 32;
    const int bA = b0 + mtile * 16 + gid;        // C rows: bA and bA+8

    float sacc[5][4];
    #pragma unroll
    for (int nt = 0; nt < 5; nt++)
        #pragma unroll
        for (int r = 0; r < 4; r++) sacc[nt][r] = 0.f;

    for (int rr = 0; rr < ITH / RPT; rr++) {
        const int ib = i0 + rr * RPT;
        // ---- stage W and x (tf32-rounded bit patterns) ----
        #pragma unroll
        for (int im = 0; im < RPT; im++) {
            const float* wp = w + (size_t)(ib + im) * (OD * DDI);
            #pragma unroll
            for (int r = 0; r < 5; r++) {
                int e = t + r * 256;                       // 0..1279 = od*8+k
                ws[im][(e >> 3) * WS + (e & 7)] = tf32r(wp[e]);
            }
            float xv = x[((size_t)(b0 + (t >> 3)) * II + (ib + im)) * DDI + (t & 7)];
            xs[im][(t >> 3) * WS + (t & 7)] = tf32r(xv);
        }
        __syncthreads();

        #pragma unroll
        for (int im = 0; im < RPT; im++) {
            const int i = ib + im;
            // A fragment (x): rows mtile*16+gid (+8), cols tig (+4)
            const int ar = mtile * 16 + gid;
            const unsigned a0 = xs[im][ar * WS + tig];
            const unsigned a1 = xs[im][(ar + 8) * WS + tig];
            const unsigned a2 = xs[im][ar * WS + tig + 4];
            const unsigned a3 = xs[im][(ar + 8) * WS + tig + 4];

            __half* rowL = g_hat + ((size_t)bA * II + i) * OD;
            __half* rowH = rowL + (size_t)8 * II * OD;

            #pragma unroll
            for (int nt = 0; nt < 5; nt++) {
                const int odb = od0w + nt * 8 + gid;       // B col for this lane
                const unsigned bf0 = ws[im][odb * WS + tig];
                const unsigned bf1 = ws[im][odb * WS + tig + 4];
                float d0 = 0.f, d1 = 0.f, d2 = 0.f, d3 = 0.f;
                asm volatile(
                    "mma.sync.aligned.m16n8k8.row.col.f32.tf32.tf32.f32 "
                    "{%0,%1,%2,%3}, {%4,%5,%6,%7}, {%8,%9}, {%0,%1,%2,%3};"
                    : "+f"(d0), "+f"(d1), "+f"(d2), "+f"(d3)
                    : "r"(a0), "r"(a1), "r"(a2), "r"(a3), "r"(bf0), "r"(bf1));
                sacc[nt][0] += d0; sacc[nt][1] += d1;
                sacc[nt][2] += d2; sacc[nt][3] += d3;
                const int oc = od0w + nt * 8 + 2 * tig;    // C cols oc, oc+1
                *(__half2*)(rowL + oc) = __floats2half2_rn(d0, d1);
                *(__half2*)(rowH + oc) = __floats2half2_rn(d2, d3);
            }
        }
        __syncthreads();
    }
    // s0 partials (c = 1/10 uniform)
    #pragma unroll
    for (int nt = 0; nt < 5; nt++) {
        const int oc = od0w + nt * 8 + 2 * tig;
        float* pL = g_spart + ((size_t)bA * NTMAX + blockIdx.x) * OD + oc;
        float* pH = g_spart + ((size_t)(bA + 8) * NTMAX + blockIdx.x) * OD + oc;
        *(float2*)pL = make_float2(0.1f * sacc[nt][0], 0.1f * sacc[nt][1]);
        *(float2*)pH = make_float2(0.1f * sacc[nt][2], 0.1f * sacc[nt][3]);
    }
}

// K2: routing pass, o-per-lane. Lane = (bh, o): lanes 0-9 & 16-25 active.
__global__ void __launch_bounds__(256) k_route() {
    const int t = threadIdx.x;
    const int warp = t >> 5, lane = t & 31;
    const int o = lane & 15;
    const bool act = (o < OO);
    const int b = blockIdx.y * 16 + warp * 2 + (lane >> 4);
    const int i0 = blockIdx.x * ITR;

    float v[16];
    const float* vp = g_vsum + b * OD + o * DDO;
    if (act) {
        #pragma unroll
        for (int r = 0; r < 4; r++) {
            float4 f = *(const float4*)(vp + 4 * r);
            v[4*r] = f.x; v[4*r+1] = f.y; v[4*r+2] = f.z; v[4*r+3] = f.w;
        }
    } else {
        #pragma unroll
        for (int k = 0; k < 16; k++) v[k] = 0.f;
    }

    float sacc[16];
    #pragma unroll
    for (int k = 0; k < 16; k++) sacc[k] = 0.f;

    #pragma unroll 2
    for (int ii = 0; ii < ITR; ii++) {
        const __half* hp = g_hat + ((size_t)b * II + (i0 + ii)) * OD + o * DDO;
        float h[16];
        float e = 0.f;
        if (act) {
            uint4 ra = *(const uint4*)hp;
            uint4 rb = *(const uint4*)(hp + 8);
            const __half2* pa = (const __half2*)&ra;
            const __half2* pb = (const __half2*)&rb;
            #pragma unroll
            for (int k = 0; k < 4; k++) {
                float2 fa = __half22float2(pa[k]);
                float2 fb = __half22float2(pb[k]);
                h[2*k]   = fa.x; h[2*k+1]   = fa.y;
                h[8+2*k] = fb.x; h[8+2*k+1] = fb.y;
            }
            float q = 0.f;
            #pragma unroll
            for (int k = 0; k < 16; k++) q += h[k] * v[k];
            e = __expf(q);                      // unstabilized, |q| small
        } else {
            #pragma unroll
            for (int k = 0; k < 16; k++) h[k] = 0.f;
        }
        float tot = e;
        #pragma unroll
        for (int s = 8; s >= 1; s >>= 1)
            tot += __shfl_xor_sync(0xffffffffu, tot, s);
        const float c = e * (1.0f / tot);
        #pragma unroll
        for (int k = 0; k < 16; k++) sacc[k] += c * h[k];
    }

    if (act) {
        float* sp = g_spart + ((size_t)b * NTMAX + blockIdx.x) * OD + o * DDO;
        #pragma unroll
        for (int r = 0; r < 4; r++)
            *(float4*)(sp + 4 * r) = make_float4(sacc[4*r], sacc[4*r+1],
                                                 sacc[4*r+2], sacc[4*r+3]);
    }
}

// K3: fixed-order partial reduction + squash. Warp per (b,o); lane = (tc, d).
__global__ void __launch_bounds__(256) k_squash(float* __restrict__ out, int mode,
                                                int ntiles) {
    const int t = threadIdx.x;
    const int warp = t >> 5, lane = t & 31;
    const int g = blockIdx.x * 8 + warp;       // (b,o), 2560 total
    const int d = lane & 15, tc = lane >> 4;
    const int b = g / OO, o = g - b * OO;
    const int od = o * DDO + d;

    float sh = 0.f;
    for (int tt = tc; tt < ntiles; tt += 2)
        sh += g_spart[((size_t)b * NTMAX + tt) * OD + od];
    const float s = sh + __shfl_xor_sync(0xffffffffu, sh, 16);

    float ss = s * s;
    #pragma unroll
    for (int r = 8; r >= 1; r >>= 1)
        ss += __shfl_xor_sync(0xffffffffu, ss, r);

    const float nrm = sqrtf(ss);
    const float v = s * (nrm / (nrm * nrm + 1.0f));
    if (tc == 0) {
        const int idx = b * OD + od;
        if (mode == 2)      out[idx] = v;
        else if (mode == 1) g_vsum[idx] += v;
        else                g_vsum[idx] = v;
    }
}

extern "C" void kernel_launch(void* const* d_in, const int* in_sizes, int n_in,
                              void* d_out, int out_size) {
    const float* x = (const float*)d_in[0];   // (B, I, DI)
    const float* w = (const float*)d_in[1];   // (I*O, DO, DI)
    float* out = (float*)d_out;               // (B, O, DO)

    dim3 ghat(NTH, BB / 32);
    dim3 grt(NTR, BB / 16);

    k_hat<<<ghat, 256>>>(x, w);
    k_squash<<<320, 256>>>(out, 0, NTH);   // v0 -> vsum
    k_route<<<grt, 256>>>();               // iter 1
    k_squash<<<320, 256>>>(out, 1, NTR);   // v1 -> vsum
    k_route<<<grt, 256>>>();               // iter 2
    k_squash<<<320, 256>>>(out, 2, NTR);   // v2 -> out
}

// round 8
// speedup vs baseline: 1.0644x; 1.0644x over previous
#include <cuda_runtime.h>
#include <cuda_fp16.h>
#include <cstdint>

#define BB 256
#define II 1152
#define OO 10
#define DDO 16
#define DDI 8
#define OD 160       // OO*DDO
#define WS 12        // smem row stride (words), conflict-free
#define CS 88        // csm row stride in uints (80 data + 8 pad)

// k_hat tiling
#define ITH 32       // i per block (hat)
#define NTH 36       // II/ITH
#define RPT 4        // i staged per sync round
// k_route tiling
#define ITR 64       // i per block (route)
#define NTR 18       // II/ITR
#define NTMAX 72     // g_spart tile stride

// Scratch (device globals: allocation-free rule)
__device__ __half g_hat[(size_t)BB * II * OD];    // ~94.4 MB
__device__ float g_spart[(size_t)BB * NTMAX * OD];
__device__ float g_vsum[BB * OD];

// f32 -> tf32 bit pattern (rna); tf32 destination is a b32 register.
__device__ __forceinline__ unsigned tf32r(float f) {
    unsigned u;
    asm("cvt.rna.tf32.f32 %0, %1;" : "=r"(u) : "f"(f));
    return u;
}

// K1: hat = x @ W^T per (b,i) via mma.m16n8k8.tf32. Block: 32 b x ITH i x 160 od.
// Warp w: m-tile (w&1) of 16 b, od-range (w>>1)*40. C staged via smem for
// coalesced g_hat stores (direct fragment stores are 4B-scattered -> 8x traffic).
__global__ void __launch_bounds__(256) k_hat(const float* __restrict__ x,
                                             const float* __restrict__ w) {
    __shared__ unsigned wsm[RPT][OD * WS];   // W[i] tf32 bits: 160 x 8 (stride 12)
    __shared__ unsigned xsm[RPT][32 * WS];   // x[i] tf32 bits:  32 x 8
    __shared__ unsigned csm[32 * CS];        // C tile: 32 b x 80 uints (+8 pad)
    const int t = threadIdx.x;
    const int warp = t >> 5, lane = t & 31;
    const int gid = lane >> 2, tig = lane & 3;
    const int mtile = warp & 1;
    const int od0w = (warp >> 1) * 40;
    const int i0 = blockIdx.x * ITH;
    const int b0 = blockIdx.y * 32;
    const int bl = mtile * 16 + gid;             // local C row (and bl+8)
    const int bA = b0 + bl;

    float sacc[5][4];
    #pragma unroll
    for (int nt = 0; nt < 5; nt++)
        #pragma unroll
        for (int r = 0; r < 4; r++) sacc[nt][r] = 0.f;

    for (int rr = 0; rr < ITH / RPT; rr++) {
        const int ib = i0 + rr * RPT;
        #pragma unroll
        for (int im = 0; im < RPT; im++) {
            const float* wp = w + (size_t)(ib + im) * (OD * DDI);
            #pragma unroll
            for (int r = 0; r < 5; r++) {
                int e = t + r * 256;                       // 0..1279 = od*8+k
                wsm[im][(e >> 3) * WS + (e & 7)] = tf32r(wp[e]);
            }
            float xv = x[((size_t)(b0 + (t >> 3)) * II + (ib + im)) * DDI + (t & 7)];
            xsm[im][(t >> 3) * WS + (t & 7)] = tf32r(xv);
        }
        __syncthreads();

        #pragma unroll
        for (int im = 0; im < RPT; im++) {
            const int i = ib + im;
            const unsigned a0 = xsm[im][bl * WS + tig];
            const unsigned a1 = xsm[im][(bl + 8) * WS + tig];
            const unsigned a2 = xsm[im][bl * WS + tig + 4];
            const unsigned a3 = xsm[im][(bl + 8) * WS + tig + 4];

            #pragma unroll
            for (int nt = 0; nt < 5; nt++) {
                const int odb = od0w + nt * 8 + gid;
                const unsigned bf0 = wsm[im][odb * WS + tig];
                const unsigned bf1 = wsm[im][odb * WS + tig + 4];
                float d0 = 0.f, d1 = 0.f, d2 = 0.f, d3 = 0.f;
                asm volatile(
                    "mma.sync.aligned.m16n8k8.row.col.f32.tf32.tf32.f32 "
                    "{%0,%1,%2,%3}, {%4,%5,%6,%7}, {%8,%9}, {%0,%1,%2,%3};"
                    : "+f"(d0), "+f"(d1), "+f"(d2), "+f"(d3)
                    : "r"(a0), "r"(a1), "r"(a2), "r"(a3), "r"(bf0), "r"(bf1));
                sacc[nt][0] += d0; sacc[nt][1] += d1;
                sacc[nt][2] += d2; sacc[nt][3] += d3;
                // C cols 2*tig, 2*tig+1 -> uint index od0w/2 + nt*4 + tig
                const int cu = (od0w >> 1) + nt * 4 + tig;
                __half2 hL = __floats2half2_rn(d0, d1);
                __half2 hH = __floats2half2_rn(d2, d3);
                csm[bl * CS + cu]       = *reinterpret_cast<unsigned*>(&hL);
                csm[(bl + 8) * CS + cu] = *reinterpret_cast<unsigned*>(&hH);
            }
            __syncthreads();
            // coalesced copy csm -> g_hat: 32 segs x 8 lanes x 10 uints
            {
                const int seg = t >> 3, off = t & 7;
                unsigned* dst = reinterpret_cast<unsigned*>(
                    g_hat + ((size_t)(b0 + seg) * II + i) * OD);
                const unsigned* src = csm + seg * CS + off;
                #pragma unroll
                for (int k = 0; k < 10; k++) dst[off + 8 * k] = src[8 * k];
            }
            __syncthreads();
        }
    }
    // s0 partials (c = 1/10 uniform)
    #pragma unroll
    for (int nt = 0; nt < 5; nt++) {
        const int oc = od0w + nt * 8 + 2 * tig;
        float* pL = g_spart + ((size_t)bA * NTMAX + blockIdx.x) * OD + oc;
        float* pH = g_spart + ((size_t)(bA + 8) * NTMAX + blockIdx.x) * OD + oc;
        *(float2*)pL = make_float2(0.1f * sacc[nt][0], 0.1f * sacc[nt][1]);
        *(float2*)pH = make_float2(0.1f * sacc[nt][2], 0.1f * sacc[nt][3]);
    }
}

// K2: routing pass, o-per-lane. Lane = (bh, o): lanes 0-9 & 16-25 active.
__global__ void __launch_bounds__(256) k_route() {
    const int t = threadIdx.x;
    const int warp = t >> 5, lane = t & 31;
    const int o = lane & 15;
    const bool act = (o < OO);
    const int b = blockIdx.y * 16 + warp * 2 + (lane >> 4);
    const int i0 = blockIdx.x * ITR;

    float v[16];
    const float* vp = g_vsum + b * OD + o * DDO;
    if (act) {
        #pragma unroll
        for (int r = 0; r < 4; r++) {
            float4 f = *(const float4*)(vp + 4 * r);
            v[4*r] = f.x; v[4*r+1] = f.y; v[4*r+2] = f.z; v[4*r+3] = f.w;
        }
    } else {
        #pragma unroll
        for (int k = 0; k < 16; k++) v[k] = 0.f;
    }

    float sacc[16];
    #pragma unroll
    for (int k = 0; k < 16; k++) sacc[k] = 0.f;

    #pragma unroll 2
    for (int ii = 0; ii < ITR; ii++) {
        const __half* hp = g_hat + ((size_t)b * II + (i0 + ii)) * OD + o * DDO;
        float h[16];
        float e = 0.f;
        if (act) {
            uint4 ra = *(const uint4*)hp;
            uint4 rb = *(const uint4*)(hp + 8);
            const __half2* pa = (const __half2*)&ra;
            const __half2* pb = (const __half2*)&rb;
            #pragma unroll
            for (int k = 0; k < 4; k++) {
                float2 fa = __half22float2(pa[k]);
                float2 fb = __half22float2(pb[k]);
                h[2*k]   = fa.x; h[2*k+1]   = fa.y;
                h[8+2*k] = fb.x; h[8+2*k+1] = fb.y;
            }
            float q = 0.f;
            #pragma unroll
            for (int k = 0; k < 16; k++) q += h[k] * v[k];
            e = __expf(q);                      // unstabilized, |q| small
        } else {
            #pragma unroll
            for (int k = 0; k < 16; k++) h[k] = 0.f;
        }
        float tot = e;
        #pragma unroll
        for (int s = 8; s >= 1; s >>= 1)
            tot += __shfl_xor_sync(0xffffffffu, tot, s);
        const float c = e * (1.0f / tot);
        #pragma unroll
        for (int k = 0; k < 16; k++) sacc[k] += c * h[k];
    }

    if (act) {
        float* sp = g_spart + ((size_t)b * NTMAX + blockIdx.x) * OD + o * DDO;
        #pragma unroll
        for (int r = 0; r < 4; r++)
            *(float4*)(sp + 4 * r) = make_float4(sacc[4*r], sacc[4*r+1],
                                                 sacc[4*r+2], sacc[4*r+3]);
    }
}

// K3: fixed-order partial reduction + squash. Warp per (b,o); lane = (tc, d).
__global__ void __launch_bounds__(256) k_squash(float* __restrict__ out, int mode,
                                                int ntiles) {
    const int t = threadIdx.x;
    const int warp = t >> 5, lane = t & 31;
    const int g = blockIdx.x * 8 + warp;       // (b,o), 2560 total
    const int d = lane & 15, tc = lane >> 4;
    const int b = g / OO, o = g - b * OO;
    const int od = o * DDO + d;

    float sh = 0.f;
    for (int tt = tc; tt < ntiles; tt += 2)
        sh += g_spart[((size_t)b * NTMAX + tt) * OD + od];
    const float s = sh + __shfl_xor_sync(0xffffffffu, sh, 16);

    float ss = s * s;
    #pragma unroll
    for (int r = 8; r >= 1; r >>= 1)
        ss += __shfl_xor_sync(0xffffffffu, ss, r);

    const float nrm = sqrtf(ss);
    const float v = s * (nrm / (nrm * nrm + 1.0f));
    if (tc == 0) {
        const int idx = b * OD + od;
        if (mode == 2)      out[idx] = v;
        else if (mode == 1) g_vsum[idx] += v;
        else                g_vsum[idx] = v;
    }
}

extern "C" void kernel_launch(void* const* d_in, const int* in_sizes, int n_in,
                              void* d_out, int out_size) {
    const float* x = (const float*)d_in[0];   // (B, I, DI)
    const float* w = (const float*)d_in[1];   // (I*O, DO, DI)
    float* out = (float*)d_out;               // (B, O, DO)

    dim3 ghat(NTH, BB / 32);
    dim3 grt(NTR, BB / 16);

    k_hat<<<ghat, 256>>>(x, w);
    k_squash<<<320, 256>>>(out, 0, NTH);   // v0 -> vsum
    k_route<<<grt, 256>>>();               // iter 1
    k_squash<<<320, 256>>>(out, 1, NTR);   // v1 -> vsum
    k_route<<<grt, 256>>>();               // iter 2
    k_squash<<<320, 256>>>(out, 2, NTR);   // v2 -> out
}